// round 12
// baseline (speedup 1.0000x reference)
#include <cuda_runtime.h>
#include <math.h>
#include <float.h>

#define BS 64
#define NA 900
#define NT 600
#define ED 256
#define AD 11
#define NC 10
#define NSEL (NA - NT)          /* 300 */
#define MD  (ED + AD)           /* 267 */
#define SORTN 1024
#define TPB_TOPK 512            /* 2 elements per thread */
#define CONF_DECAY 0.6f

#define MQUADS_PER_B (NA / 4)    /* 225 */
#define QQUADS_PER_B (NT / 4)    /* 150 */
#define QUADS_PER_B (MQUADS_PER_B + QQUADS_PER_B) /* 375 */
#define TOTQUADS (BS * QUADS_PER_B)               /* 24000 warps */

// Scratch (no device mallocs allowed)
__device__ int g_src[BS * NA];   // per (b,i): >=0 -> instance row s ; <0 -> cached row -(s+1)
__device__ int g_idx2[BS * NT];  // second top-k indices into 0..NA-1

// ---------------------------------------------------------------------------
// Dtype-agnostic mask read (bool may arrive as uint8 / int32 / float32)
// ---------------------------------------------------------------------------
__device__ __forceinline__ bool read_mask(const void* mp, int b) {
    const unsigned char* u8 = (const unsigned char*)mp;
    bool any_gt1 = false, nonmult4 = false;
    #pragma unroll
    for (int i = 0; i < 64; i++) {
        unsigned char v = u8[i];
        if (v > 1) any_gt1 = true;
        if (v != 0 && (i & 3) != 0) nonmult4 = true;
    }
    if (any_gt1)  return ((const float*)mp)[b] != 0.0f;
    if (nonmult4) return u8[b] != 0;
    return ((const int*)mp)[b] != 0;
}

// ---------------------------------------------------------------------------
// Order-preserving float<->uint + (key, idx) u64 packing. Descending u64 sort
// == descending key, ascending index on ties (jax.lax.top_k semantics).
// ---------------------------------------------------------------------------
__device__ __forceinline__ unsigned int ord_of_float(float f) {
    unsigned int u = __float_as_uint(f);
    return (u & 0x80000000u) ? ~u : (u | 0x80000000u);
}
__device__ __forceinline__ float float_of_ord(unsigned int o) {
    unsigned int u = (o & 0x80000000u) ? (o & 0x7FFFFFFFu) : ~o;
    return __uint_as_float(u);
}
__device__ __forceinline__ unsigned long long pack_ki(float k, int idx) {
    return ((unsigned long long)ord_of_float(k) << 32)
         | (unsigned long long)(0xFFFFFFFFu - (unsigned)idx);
}
__device__ __forceinline__ int idx_of_pack(unsigned long long v) {
    return (int)(0xFFFFFFFFu - (unsigned)(v & 0xFFFFFFFFu));
}

// ---------------------------------------------------------------------------
// Kernel 1: 128 blocks of 512 threads, 2 elements/thread bitonic sort.
//   Block (2b+0): sort conf_max          -> g_src (uses mask, top-300 "sel")
//   Block (2b+1): sort conf_c (sigmoid)  -> newconf + g_idx2 (top-600)
// Element i = t + 512*e. j<32: shfl. 32<=j<=256: shared. j=512: intra-thread.
// ---------------------------------------------------------------------------
__global__ __launch_bounds__(TPB_TOPK) void topk_kernel(
    const float* __restrict__ conf,      // BS,NA,NC
    const float* __restrict__ prevconf,  // BS,NT
    const void*  __restrict__ mask,      // BS (bool; dtype unknown)
    float* __restrict__ newconf_out)     // BS,NT
{
    __shared__ unsigned long long buf[2][SORTN];
    __shared__ int sel[NSEL];

    const int b    = blockIdx.x >> 1;
    const int role = blockIdx.x & 1;
    const int t    = threadIdx.x;

    unsigned long long v[2];

    // build keys for elements t + 512e
    #pragma unroll
    for (int e = 0; e < 2; e++) {
        const int i = t + 512 * e;
        if (i < NA) {
            const float* p = conf + ((size_t)b * NA + i) * NC;
            float m = p[0];
            #pragma unroll
            for (int c = 1; c < NC; c++) m = fmaxf(m, p[c]);
            if (role == 0) {
                v[e] = pack_ki(m, i);
            } else {
                float s = 1.0f / (1.0f + expf(-m));
                if (i < NT) s = fmaxf(prevconf[b * NT + i] * CONF_DECAY, s);
                v[e] = pack_ki(s, i);
            }
        } else {
            v[e] = 0ULL;
        }
    }

    // bitonic sort, descending. keep_max = ((i&j)==0) == ((i&k)==0)
    int pb = 0;
    #pragma unroll
    for (int k = 2; k <= SORTN; k <<= 1) {
        #pragma unroll
        for (int j = k >> 1; j > 0; j >>= 1) {
            if (j >= 512) {
                // intra-thread swap between e=0 (lower) and e=1. k==1024 here,
                // so (i & k)==0 always -> descending -> keep max in e=0.
                unsigned long long lo = v[0], hi = v[1];
                v[0] = lo > hi ? lo : hi;
                v[1] = lo > hi ? hi : lo;
            } else if (j >= 32) {
                #pragma unroll
                for (int e = 0; e < 2; e++) buf[pb][t + 512 * e] = v[e];
                __syncthreads();
                #pragma unroll
                for (int e = 0; e < 2; e++) {
                    const int i = t + 512 * e;
                    unsigned long long u = buf[pb][i ^ j];
                    const bool keep_max = (((i & j) == 0) == ((i & k) == 0));
                    v[e] = keep_max ? (v[e] > u ? v[e] : u)
                                    : (v[e] < u ? v[e] : u);
                }
                pb ^= 1;
            } else {
                #pragma unroll
                for (int e = 0; e < 2; e++) {
                    unsigned long long u = __shfl_xor_sync(0xFFFFFFFFu, v[e], j);
                    const int i = t + 512 * e;
                    const bool keep_max = (((i & j) == 0) == ((i & k) == 0));
                    v[e] = keep_max ? (v[e] > u ? v[e] : u)
                                    : (v[e] < u ? v[e] : u);
                }
            }
        }
    }

    // thread t holds sorted positions t and t+512 (descending)
    if (role == 0) {
        if (t < NSEL) sel[t] = idx_of_pack(v[0]);   // positions 0..299 all in e=0
        __syncthreads();
        const bool m = read_mask(mask, b);
        #pragma unroll
        for (int e = 0; e < 2; e++) {
            const int i = t + 512 * e;
            if (i < NA) {
                int s;
                if (m) s = (i < NT) ? -(i + 1) : sel[i - NT];
                else   s = i;
                g_src[b * NA + i] = s;
            }
        }
    } else {
        // positions 0..511 in e=0, 512..599 in e=1 (t<88)
        newconf_out[b * NT + t] = float_of_ord((unsigned)(v[0] >> 32));
        g_idx2[b * NT + t] = idx_of_pack(v[0]);
        if (t < NT - 512) {
            const int p = t + 512;
            newconf_out[b * NT + p] = float_of_ord((unsigned)(v[1] >> 32));
            g_idx2[b * NT + p] = idx_of_pack(v[1]);
        }
    }
}

// ---------------------------------------------------------------------------
// Kernel 2 (fused gather): one warp per QUAD of rows, batch-interleaved order.
// All 4 rows of a quad are the same kind (900 and 600 both divisible by 4).
// Index loads (int4) issued up-front -> 4x chain-level MLP per warp.
// ---------------------------------------------------------------------------
__global__ __launch_bounds__(256) void gather_kernel(
    const float* __restrict__ inst,   // BS,NA,ED
    const float* __restrict__ anch,   // BS,NA,AD
    const float* __restrict__ cfeat,  // BS,NT,ED
    const float* __restrict__ canch,  // BS,NT,AD
    float* __restrict__ merged,       // BS,NA,MD
    float* __restrict__ cf,           // BS,NT,ED
    float* __restrict__ ca)           // BS,NT,AD
{
    const int w    = (int)((blockIdx.x * blockDim.x + threadIdx.x) >> 5);
    const int lane = threadIdx.x & 31;
    if (w >= TOTQUADS) return;

    const int b  = w / QUADS_PER_B;
    const int qr = w - b * QUADS_PER_B;

    if (qr < MQUADS_PER_B) {
        // ----- four merged rows -----
        const int r0 = 4 * qr;
        const int4 ss = *(const int4*)(g_src + b * NA + r0);
        int sv[4] = {ss.x, ss.y, ss.z, ss.w};

        const float* srcF[4];
        const float* srcA[4];
        #pragma unroll
        for (int r = 0; r < 4; r++) {
            if (sv[r] >= 0) {
                const size_t rr = (size_t)b * NA + (unsigned)sv[r];
                srcF[r] = inst + rr * ED;
                srcA[r] = anch + rr * AD;
            } else {
                const size_t rr = (size_t)b * NT + (unsigned)(-sv[r] - 1);
                srcF[r] = cfeat + rr * ED;
                srcA[r] = canch + rr * AD;
            }
        }

        float f[4][8];
        float a[4];
        #pragma unroll
        for (int r = 0; r < 4; r++)
            #pragma unroll
            for (int c = 0; c < 8; c++)
                f[r][c] = srcF[r][c * 32 + lane];
        #pragma unroll
        for (int r = 0; r < 4; r++)
            a[r] = (lane < AD) ? srcA[r][lane] : 0.0f;

        float* dst = merged + (size_t)(b * NA + r0) * MD;
        #pragma unroll
        for (int r = 0; r < 4; r++) {
            #pragma unroll
            for (int c = 0; c < 8; c++)
                __stcs(dst + (size_t)r * MD + c * 32 + lane, f[r][c]);
            if (lane < AD) __stcs(dst + (size_t)r * MD + ED + lane, a[r]);
        }
    } else {
        // ----- four cf (+ca) rows -----
        const int q0 = b * NT + 4 * (qr - MQUADS_PER_B);
        const int4 ii = *(const int4*)(g_idx2 + q0);
        int iv[4] = {ii.x, ii.y, ii.z, ii.w};

        int sv[4];
        #pragma unroll
        for (int r = 0; r < 4; r++) sv[r] = g_src[b * NA + iv[r]];

        const float4* srcF[4];
        const float*  srcA[4];
        #pragma unroll
        for (int r = 0; r < 4; r++) {
            if (sv[r] >= 0) {
                const size_t rr = (size_t)b * NA + (unsigned)sv[r];
                srcF[r] = (const float4*)(inst + rr * ED);
                srcA[r] = anch + rr * AD;
            } else {
                const size_t rr = (size_t)b * NT + (unsigned)(-sv[r] - 1);
                srcF[r] = (const float4*)(cfeat + rr * ED);
                srcA[r] = canch + rr * AD;
            }
        }

        float4 vv[4][2];
        float  a[4];
        #pragma unroll
        for (int r = 0; r < 4; r++) {
            vv[r][0] = srcF[r][lane];
            vv[r][1] = srcF[r][lane + 32];
        }
        #pragma unroll
        for (int r = 0; r < 4; r++)
            a[r] = (lane < AD) ? srcA[r][lane] : 0.0f;

        float4* dstF = (float4*)(cf + (size_t)q0 * ED);
        #pragma unroll
        for (int r = 0; r < 4; r++) {
            __stcs(dstF + r * (ED / 4) + lane,      vv[r][0]);
            __stcs(dstF + r * (ED / 4) + lane + 32, vv[r][1]);
        }
        if (lane < AD) {
            #pragma unroll
            for (int r = 0; r < 4; r++)
                __stcs(ca + (size_t)(q0 + r) * AD + lane, a[r]);
        }
    }
}

// ---------------------------------------------------------------------------
extern "C" void kernel_launch(void* const* d_in, const int* in_sizes, int n_in,
                              void* d_out, int out_size)
{
    const float* inst  = (const float*)d_in[0];
    const float* anch  = (const float*)d_in[1];
    const float* conf  = (const float*)d_in[2];
    const float* cfeat = (const float*)d_in[3];
    const float* canch = (const float*)d_in[4];
    const float* prevc = (const float*)d_in[5];
    const void*  mask  = (const void*)d_in[6];

    float* out     = (float*)d_out;
    float* merged  = out;                                      // BS*NA*MD
    float* newconf = merged + (size_t)BS * NA * MD;            // BS*NT
    float* cf      = newconf + (size_t)BS * NT;                // BS*NT*ED
    float* ca      = cf + (size_t)BS * NT * ED;                // BS*NT*AD

    topk_kernel<<<2 * BS, TPB_TOPK>>>(conf, prevc, mask, newconf);

    const int warps_per_block = 256 / 32;
    const int blocks = (TOTQUADS + warps_per_block - 1) / warps_per_block;
    gather_kernel<<<blocks, 256>>>(inst, anch, cfeat, canch, merged, cf, ca);
}